// round 4
// baseline (speedup 1.0000x reference)
#include <cuda_runtime.h>
#include <cuda_bf16.h>
#include <cstdint>
#include <math.h>

#define NPTS 8192
#define NMAT ((size_t)NPTS * (size_t)NPTS)
#define TS   512
#define NT   16
#define NPAIRS 136         /* NT*(NT+1)/2 */

#define EPSV     0.05f
#define INV_EPS  20.0f
#define CLOGN    0.45054567f   /* eps * log(8192) */

// ---- scratch (static device memory; allocation-free) ----
__device__ __nv_bfloat16 g_Kxy[NMAT];
__device__ __nv_bfloat16 g_Kyx[NMAT];
__device__ __nv_bfloat16 g_Kxx[NMAT];   // lower-triangle tiles only
__device__ __nv_bfloat16 g_Kyy[NMAT];   // lower-triangle tiles only

__device__ float g_P[2][2][NPTS][NT];   // sym partials [parity][xx|yy][row][coltile]
__device__ float g_Pf[NPTS][2];         // xy partials: f side (written even t)
__device__ float g_Pg[NPTS][2];         // xy partials: g side (written odd t)
__device__ float g_vals[6][NPTS];       // staged final values f,g,hx99,hx100,hy99,hy100
__device__ float g_cham[NPTS];

__device__ __forceinline__ float bf_lo(unsigned u){ return __uint_as_float(u << 16); }
__device__ __forceinline__ float bf_hi(unsigned u){ return __uint_as_float(u & 0xffff0000u); }

__global__ void init_kernel(){
  int i = blockIdx.x * blockDim.x + threadIdx.x;
  if (i < NPTS){
    g_Pf[i][0] = 4096.f; g_Pf[i][1] = 4096.f;   // sum = 8192 -> w = 1
    g_Pg[i][0] = 4096.f; g_Pg[i][1] = 4096.f;
  }
  int tot = 2 * NPTS * NT;                       // parity 0 only
  for (int j = i; j < tot; j += gridDim.x * blockDim.x)
    (&g_P[0][0][0][0])[j] = 512.f;               // sum16 = 8192 -> w = 1
}

// One block per row. K[row][:] = exp(-sqrt(d2+1e-12)/eps) in bf16.
// which: 0=Kxy  1=Kyx (+chamfer row mins)  2=Kxx (triangle)  3=Kyy (triangle)
__global__ void __launch_bounds__(256) fill_kernel(const float* __restrict__ Apts,
                                                   const float* __restrict__ Bpts,
                                                   int which){
  __nv_bfloat16* K; float* rowmin = nullptr;
  if      (which == 0)  K = g_Kxy;
  else if (which == 1){ K = g_Kyx; rowmin = g_cham; }
  else if (which == 2)  K = g_Kxx;
  else                  K = g_Kyy;

  int row = blockIdx.x;
  int climit = (which >= 2) ? (((row >> 9) + 1) << 9) : NPTS;
  float4 ap = reinterpret_cast<const float4*>(Apts)[row];
  float na = ap.x*ap.x + ap.y*ap.y + ap.z*ap.z;
  float mn = INFINITY;
  unsigned* Kout = reinterpret_cast<unsigned*>(K + ((size_t)row << 13));
  const float4* Bv = reinterpret_cast<const float4*>(Bpts);

  for (int k = threadIdx.x; k < climit/2; k += 256){
    float4 b0 = Bv[2*k], b1 = Bv[2*k + 1];
    float d0 = fmaxf(na + (b0.x*b0.x + b0.y*b0.y + b0.z*b0.z)
                        - 2.f*(ap.x*b0.x + ap.y*b0.y + ap.z*b0.z), 0.f);
    float d1 = fmaxf(na + (b1.x*b1.x + b1.y*b1.y + b1.z*b1.z)
                        - 2.f*(ap.x*b1.x + ap.y*b1.y + ap.z*b1.z), 0.f);
    mn = fminf(mn, fminf(d0, d1));
    float e0 = __expf(-INV_EPS * sqrtf(d0 + 1e-12f));
    float e1 = __expf(-INV_EPS * sqrtf(d1 + 1e-12f));
    __nv_bfloat162 p = __floats2bfloat162_rn(e0, e1);
    Kout[k] = *reinterpret_cast<unsigned*>(&p);
  }

  if (rowmin){
    __shared__ float sredm[8];
    int lane = threadIdx.x & 31, wid = threadIdx.x >> 5;
    #pragma unroll
    for (int o = 16; o; o >>= 1) mn = fminf(mn, __shfl_xor_sync(0xffffffffu, mn, o));
    if (lane == 0) sredm[wid] = mn;
    __syncthreads();
    if (threadIdx.x == 0){
      float m = sredm[0];
      #pragma unroll
      for (int w = 1; w < 8; w++) m = fminf(m, sredm[w]);
      rowmin[row] = m;
    }
  }
}

// Blocks 0..511: xy chain, 32 rows x 4096 cols each (rowgrp = b>>1, half = b&1).
// Blocks 512..783: symmetric lower-triangle 512x512 tiles (xx: 136, yy: 136).
__global__ void __launch_bounds__(256) step_kernel(int t){
  __shared__ __align__(16) float sbuf[5120];
  int tid = threadIdx.x, lane = tid & 31, wid = tid >> 5;
  int b = blockIdx.x;
  bool even = (t & 1) == 0;

  if (b < 512){
    // ---------------- xy chain: half-row matvec ----------------
    const __nv_bfloat16* K = even ? g_Kxy : g_Kyx;
    const float (*Pin)[2] = even ? g_Pg : g_Pf;   // opposite side's partials
    float (*Pout)[2]      = even ? g_Pf : g_Pg;
    int rowgrp = b >> 1, half = b & 1;
    int cbase = half << 12;

    float* sw = sbuf;   // 4096 w values for this half
    for (int i = tid; i < 4096; i += 256){
      float2 pp = *reinterpret_cast<const float2*>(Pin[cbase + i]);
      sw[i] = 8192.f / fmaxf(pp.x + pp.y, 1e-35f);
    }
    __syncthreads();

    int base = rowgrp << 5;
    #pragma unroll
    for (int p = 0; p < 2; p++){
      int row0 = base + (wid << 2) + (p << 1);
      const uint4* K0 = reinterpret_cast<const uint4*>(K + ((size_t)row0 << 13) + cbase);
      const uint4* K1 = reinterpret_cast<const uint4*>(K + ((size_t)(row0 + 1) << 13) + cbase);
      float s0 = 0.f, s1 = 0.f;
      #pragma unroll 4
      for (int it = lane; it < 512; it += 32){
        uint4 a = K0[it];
        uint4 c = K1[it];
        const float4* vp = reinterpret_cast<const float4*>(sw + (it << 3));
        float4 v0 = vp[0], v1 = vp[1];
        s0 += bf_lo(a.x)*v0.x + bf_hi(a.x)*v0.y + bf_lo(a.y)*v0.z + bf_hi(a.y)*v0.w
            + bf_lo(a.z)*v1.x + bf_hi(a.z)*v1.y + bf_lo(a.w)*v1.z + bf_hi(a.w)*v1.w;
        s1 += bf_lo(c.x)*v0.x + bf_hi(c.x)*v0.y + bf_lo(c.y)*v0.z + bf_hi(c.y)*v0.w
            + bf_lo(c.z)*v1.x + bf_hi(c.z)*v1.y + bf_lo(c.w)*v1.z + bf_hi(c.w)*v1.w;
      }
      #pragma unroll
      for (int o = 16; o; o >>= 1){
        s0 += __shfl_xor_sync(0xffffffffu, s0, o);
        s1 += __shfl_xor_sync(0xffffffffu, s1, o);
      }
      if (lane == 0){
        Pout[row0][half]     = s0;
        Pout[row0 + 1][half] = s1;
      }
    }
  } else {
    // ------------- symmetric chains: lower-triangle tiles -------------
    int sb  = b - 512;
    int mat = (sb >= NPAIRS) ? 1 : 0;
    int p   = mat ? sb - NPAIRS : sb;
    int A = (int)((sqrtf(8.f * p + 1.f) - 1.f) * 0.5f);
    while ((A + 1) * (A + 2) / 2 <= p) A++;
    while (A * (A + 1) / 2 > p) A--;
    int B = p - ((A * (A + 1)) >> 1);
    bool diag = (A == B);

    const __nv_bfloat16* K = mat ? g_Kyy : g_Kxx;
    const float (*Pin)[NT] = g_P[t & 1][mat];
    float (*Pout)[NT]      = g_P[(t + 1) & 1][mat];

    float* wcol = sbuf;            // 512
    float* wrow = sbuf + TS;       // 512
    float* cs   = sbuf + 2 * TS;   // 8 * 512 staging

    // Recompute w^{(t)} slices from partials (L2-resident).
    for (int i = tid; i < TS; i += 256){
      int rB = B * TS + i, rA = A * TS + i;
      const float4* pb = reinterpret_cast<const float4*>(Pin[rB]);
      float4 q0 = pb[0], q1 = pb[1], q2 = pb[2], q3 = pb[3];
      float sB = (q0.x+q0.y+q0.z+q0.w) + (q1.x+q1.y+q1.z+q1.w)
               + (q2.x+q2.y+q2.z+q2.w) + (q3.x+q3.y+q3.z+q3.w);
      wcol[i] = 8192.f / fmaxf(sB, 1e-35f);
      const float4* pa = reinterpret_cast<const float4*>(Pin[rA]);
      float4 r0 = pa[0], r1 = pa[1], r2 = pa[2], r3 = pa[3];
      float sA = (r0.x+r0.y+r0.z+r0.w) + (r1.x+r1.y+r1.z+r1.w)
               + (r2.x+r2.y+r2.z+r2.w) + (r3.x+r3.y+r3.z+r3.w);
      wrow[i] = 8192.f / fmaxf(sA, 1e-35f);
    }
    __syncthreads();

    // R2's proven 1-row-per-warp-iteration loop (no spills).
    float4 acc[4];
    #pragma unroll
    for (int i = 0; i < 4; i++) acc[i] = make_float4(0.f, 0.f, 0.f, 0.f);

    for (int r = wid; r < TS; r += 8){
      const uint4* Kr = reinterpret_cast<const uint4*>(
          K + (((size_t)(A * TS + r)) << 13) + (size_t)B * TS);
      float wr = wrow[r];
      float rd = 0.f;
      #pragma unroll
      for (int i = 0; i < 2; i++){
        uint4 kk = Kr[(i << 5) + lane];
        const float4* wp = reinterpret_cast<const float4*>(wcol + (i << 8) + (lane << 3));
        float4 w0 = wp[0], w1 = wp[1];
        float k0 = bf_lo(kk.x), k1 = bf_hi(kk.x), k2 = bf_lo(kk.y), k3 = bf_hi(kk.y);
        float k4 = bf_lo(kk.z), k5 = bf_hi(kk.z), k6 = bf_lo(kk.w), k7 = bf_hi(kk.w);
        rd += k0*w0.x + k1*w0.y + k2*w0.z + k3*w0.w
            + k4*w1.x + k5*w1.y + k6*w1.z + k7*w1.w;
        if (!diag){
          acc[2*i].x   += k0 * wr;  acc[2*i].y   += k1 * wr;
          acc[2*i].z   += k2 * wr;  acc[2*i].w   += k3 * wr;
          acc[2*i+1].x += k4 * wr;  acc[2*i+1].y += k5 * wr;
          acc[2*i+1].z += k6 * wr;  acc[2*i+1].w += k7 * wr;
        }
      }
      #pragma unroll
      for (int o = 16; o; o >>= 1) rd += __shfl_xor_sync(0xffffffffu, rd, o);
      if (lane == 0)
        Pout[A * TS + r][B] = rd;
    }

    if (!diag){
      #pragma unroll
      for (int i = 0; i < 2; i++){
        *reinterpret_cast<float4*>(cs + wid * TS + (i << 8) + (lane << 3))     = acc[2*i];
        *reinterpret_cast<float4*>(cs + wid * TS + (i << 8) + (lane << 3) + 4) = acc[2*i+1];
      }
      __syncthreads();
      for (int c = tid; c < TS; c += 256){
        float s = 0.f;
        #pragma unroll
        for (int w = 0; w < 8; w++) s += cs[w * TS + c];
        Pout[B * TS + c][A] = s;
      }
    }
  }
}

// Convert final partials into values: f, g, hx99, hx100, hy99, hy100.
__global__ void __launch_bounds__(256) finish_kernel(){
  int idx = blockIdx.x * 256 + threadIdx.x;    // 0 .. 6*8192-1
  int a = idx >> 13;
  int r = idx & (NPTS - 1);
  float s;
  if (a == 0){       s = g_Pf[r][0] + g_Pf[r][1]; }
  else if (a == 1){  s = g_Pg[r][0] + g_Pg[r][1]; }
  else {
    int parity = (a == 2 || a == 4) ? 1 : 0;   // h99 in parity 1, h100 in parity 0
    int mat    = (a <= 3) ? 0 : 1;
    const float4* Pp = reinterpret_cast<const float4*>(g_P[parity][mat][r]);
    float4 p0 = Pp[0], p1 = Pp[1], p2 = Pp[2], p3 = Pp[3];
    s = (p0.x+p0.y+p0.z+p0.w) + (p1.x+p1.y+p1.z+p1.w)
      + (p2.x+p2.y+p2.z+p2.w) + (p3.x+p3.y+p3.z+p3.w);
  }
  g_vals[a][r] = CLOGN - EPSV * __logf(fmaxf(s, 1e-35f));
}

__global__ void final_kernel(float* out){
  __shared__ float sred[8];
  int tid = threadIdx.x, lane = tid & 31, wid = tid >> 5;
  const float* arrs[7] = { g_vals[0], g_vals[1], g_vals[2], g_vals[3],
                           g_vals[4], g_vals[5], g_cham };
  float totals[7];
  for (int a = 0; a < 7; a++){
    float s = 0.f;
    for (int i = tid; i < NPTS; i += 256) s += arrs[a][i];
    #pragma unroll
    for (int o = 16; o; o >>= 1) s += __shfl_xor_sync(0xffffffffu, s, o);
    __syncthreads();
    if (lane == 0) sred[wid] = s;
    __syncthreads();
    if (tid == 0){
      float tt = 0.f;
      #pragma unroll
      for (int w = 0; w < 8; w++) tt += sred[w];
      totals[a] = tt;
    }
  }
  if (tid == 0){
    const float invN = 1.f / (float)NPTS;
    float ot_xy = (totals[0] + totals[1]) * invN;
    float ot_xx = (totals[2] + totals[3]) * invN;
    float ot_yy = (totals[4] + totals[5]) * invN;
    float cham  = totals[6] * invN;
    float emd = ot_xy - 0.5f * ot_xx - 0.5f * ot_yy;
    out[0] = 0.2f * cham + 0.8f * emd;
  }
}

extern "C" void kernel_launch(void* const* d_in, const int* in_sizes, int n_in,
                              void* d_out, int out_size){
  const float* pred = (const float*)d_in[0];
  const float* gt   = (const float*)d_in[1];
  float* out = (float*)d_out;

  init_kernel<<<256, 256>>>();
  fill_kernel<<<NPTS, 256>>>(pred, gt,   0);   // Kxy
  fill_kernel<<<NPTS, 256>>>(gt,   pred, 1);   // Kyx + chamfer row mins
  fill_kernel<<<NPTS, 256>>>(pred, pred, 2);   // Kxx (lower triangle)
  fill_kernel<<<NPTS, 256>>>(gt,   gt,   3);   // Kyy (lower triangle)

  for (int t = 0; t < 100; t++)
    step_kernel<<<512 + 2 * NPAIRS, 256>>>(t);

  finish_kernel<<<192, 256>>>();
  final_kernel<<<1, 256>>>(out);
}

// round 5
// speedup vs baseline: 1.8310x; 1.8310x over previous
#include <cuda_runtime.h>
#include <cuda_bf16.h>
#include <cstdint>
#include <math.h>

#define NPTS 8192
#define NMAT ((size_t)NPTS * (size_t)NPTS)
#define TS   512
#define NT   16
#define NPAIRS 136                      /* NT*(NT+1)/2 */
#define TILE_ELEMS ((size_t)TS * TS)    /* 262144 */

#define EPSV     0.05f
#define INV_EPS  20.0f
#define CLOGN    0.45054567f   /* eps * log(8192) */

// ---- scratch (static device memory; allocation-free) ----
__device__ __nv_bfloat16 g_Kxy[NMAT];
__device__ __nv_bfloat16 g_Kyx[NMAT];
__device__ __nv_bfloat16 g_Kxx[NPAIRS * TILE_ELEMS];  // packed lower-triangle tiles
__device__ __nv_bfloat16 g_Kyy[NPAIRS * TILE_ELEMS];  // packed lower-triangle tiles

__device__ float g_P[2][NPTS][NT];      // symmetric-matvec partials [xx|yy][row][coltile]

__device__ float g_f[NPTS], g_g[NPTS], g_wf[NPTS], g_wg[NPTS];
__device__ float g_hx[2][NPTS], g_whx[2][NPTS];
__device__ float g_hy[2][NPTS], g_why[2][NPTS];
__device__ float g_cham[NPTS];

__device__ __forceinline__ float bf_lo(unsigned u){ return __uint_as_float(u << 16); }
__device__ __forceinline__ float bf_hi(unsigned u){ return __uint_as_float(u & 0xffff0000u); }

__device__ __forceinline__ void decode_pair(int p, int& A, int& B){
  int a = (int)((sqrtf(8.f * p + 1.f) - 1.f) * 0.5f);
  while ((a + 1) * (a + 2) / 2 <= p) a++;
  while (a * (a + 1) / 2 > p) a--;
  A = a; B = p - ((a * (a + 1)) >> 1);
}

__global__ void init_kernel(){
  int i = blockIdx.x * blockDim.x + threadIdx.x;
  if (i < NPTS){
    g_wf[i] = 1.f; g_wg[i] = 1.f;
    g_whx[0][i] = 1.f; g_whx[1][i] = 1.f;
    g_why[0][i] = 1.f; g_why[1][i] = 1.f;
    g_f[i] = 0.f; g_g[i] = 0.f;
    g_hx[0][i] = 0.f; g_hx[1][i] = 0.f;
    g_hy[0][i] = 0.f; g_hy[1][i] = 0.f;
  }
}

// xy fills: one block per row (dense). which: 0=Kxy  1=Kyx (+chamfer row mins)
__global__ void __launch_bounds__(256) fill_kernel(const float* __restrict__ Apts,
                                                   const float* __restrict__ Bpts,
                                                   int which){
  __nv_bfloat16* K = (which == 0) ? g_Kxy : g_Kyx;
  float* rowmin = (which == 1) ? g_cham : nullptr;

  int row = blockIdx.x;
  float4 ap = reinterpret_cast<const float4*>(Apts)[row];
  float na = ap.x*ap.x + ap.y*ap.y + ap.z*ap.z;
  float mn = INFINITY;
  unsigned* Kout = reinterpret_cast<unsigned*>(K + ((size_t)row << 13));
  const float4* Bv = reinterpret_cast<const float4*>(Bpts);

  for (int k = threadIdx.x; k < NPTS/2; k += 256){
    float4 b0 = Bv[2*k], b1 = Bv[2*k + 1];
    float d0 = fmaxf(na + (b0.x*b0.x + b0.y*b0.y + b0.z*b0.z)
                        - 2.f*(ap.x*b0.x + ap.y*b0.y + ap.z*b0.z), 0.f);
    float d1 = fmaxf(na + (b1.x*b1.x + b1.y*b1.y + b1.z*b1.z)
                        - 2.f*(ap.x*b1.x + ap.y*b1.y + ap.z*b1.z), 0.f);
    mn = fminf(mn, fminf(d0, d1));
    float e0 = __expf(-INV_EPS * sqrtf(d0 + 1e-12f));
    float e1 = __expf(-INV_EPS * sqrtf(d1 + 1e-12f));
    __nv_bfloat162 p = __floats2bfloat162_rn(e0, e1);
    Kout[k] = *reinterpret_cast<unsigned*>(&p);
  }

  if (rowmin){
    __shared__ float sredm[8];
    int lane = threadIdx.x & 31, wid = threadIdx.x >> 5;
    #pragma unroll
    for (int o = 16; o; o >>= 1) mn = fminf(mn, __shfl_xor_sync(0xffffffffu, mn, o));
    if (lane == 0) sredm[wid] = mn;
    __syncthreads();
    if (threadIdx.x == 0){
      float m = sredm[0];
      #pragma unroll
      for (int w = 1; w < 8; w++) m = fminf(m, sredm[w]);
      rowmin[row] = m;
    }
  }
}

// Packed symmetric fills: blocks 0..(NPAIRS*64-1) -> Kxx, next NPAIRS*64 -> Kyy.
// Each block: 8 rows of one 512x512 tile (one row per warp).
__global__ void __launch_bounds__(256) fill_sym_kernel(const float* __restrict__ xpts,
                                                       const float* __restrict__ ypts){
  __shared__ __align__(16) float4 sB[TS];
  int blk = blockIdx.x;
  int mat = (blk >= NPAIRS * 64) ? 1 : 0;
  if (mat) blk -= NPAIRS * 64;
  int p  = blk >> 6;
  int rr = (blk & 63) << 3;
  int A, B; decode_pair(p, A, B);

  const float* pts = mat ? ypts : xpts;
  __nv_bfloat16* out = (mat ? g_Kyy : g_Kxx) + (size_t)p * TILE_ELEMS;

  const float4* P4 = reinterpret_cast<const float4*>(pts);
  for (int i = threadIdx.x; i < TS; i += 256) sB[i] = P4[B * TS + i];
  __syncthreads();

  int lane = threadIdx.x & 31, wid = threadIdx.x >> 5;
  int r = rr + wid;
  float4 ap = P4[A * TS + r];
  float na = ap.x*ap.x + ap.y*ap.y + ap.z*ap.z;
  unsigned* orow = reinterpret_cast<unsigned*>(out + ((size_t)r << 9));

  #pragma unroll
  for (int c0 = 0; c0 < 8; c0++){
    int c = (c0 << 5) + lane;          // packed-pair index: cols 2c, 2c+1
    float4 b0 = sB[2*c], b1 = sB[2*c + 1];
    float d0 = fmaxf(na + (b0.x*b0.x + b0.y*b0.y + b0.z*b0.z)
                        - 2.f*(ap.x*b0.x + ap.y*b0.y + ap.z*b0.z), 0.f);
    float d1 = fmaxf(na + (b1.x*b1.x + b1.y*b1.y + b1.z*b1.z)
                        - 2.f*(ap.x*b1.x + ap.y*b1.y + ap.z*b1.z), 0.f);
    float e0 = __expf(-INV_EPS * sqrtf(d0 + 1e-12f));
    float e1 = __expf(-INV_EPS * sqrtf(d1 + 1e-12f));
    __nv_bfloat162 pk = __floats2bfloat162_rn(e0, e1);
    orow[c] = *reinterpret_cast<unsigned*>(&pk);
  }
}

// Blocks 0..255: xy chain, 32 full rows each.
// Blocks 256..527: packed symmetric tiles (xx: 136, yy: 136).
__global__ void __launch_bounds__(256) step_kernel(int t){
  __shared__ __align__(16) float sbuf[NPTS];
  int tid = threadIdx.x, lane = tid & 31, wid = tid >> 5;
  int b = blockIdx.x;
  bool even = (t & 1) == 0;

  if (b < 256){
    // ---------------- xy chain: full-row matvec ----------------
    const __nv_bfloat16* K = even ? g_Kxy : g_Kyx;
    const float* win  = even ? g_wg : g_wf;
    float* vout = even ? g_f  : g_g;
    float* wout = even ? g_wf : g_wg;

    for (int i = tid; i < NPTS/4; i += 256)
      reinterpret_cast<float4*>(sbuf)[i] = reinterpret_cast<const float4*>(win)[i];
    __syncthreads();

    int base = b << 5;
    #pragma unroll
    for (int p = 0; p < 2; p++){
      int row0 = base + (wid << 2) + (p << 1);
      const uint4* K0 = reinterpret_cast<const uint4*>(K + ((size_t)row0 << 13));
      const uint4* K1 = reinterpret_cast<const uint4*>(K + ((size_t)(row0 + 1) << 13));
      float s0 = 0.f, s1 = 0.f;
      #pragma unroll 4
      for (int it = lane; it < NPTS/8; it += 32){
        uint4 a = K0[it];
        uint4 c = K1[it];
        const float4* vp = reinterpret_cast<const float4*>(sbuf + (it << 3));
        float4 v0 = vp[0], v1 = vp[1];
        s0 += bf_lo(a.x)*v0.x + bf_hi(a.x)*v0.y + bf_lo(a.y)*v0.z + bf_hi(a.y)*v0.w
            + bf_lo(a.z)*v1.x + bf_hi(a.z)*v1.y + bf_lo(a.w)*v1.z + bf_hi(a.w)*v1.w;
        s1 += bf_lo(c.x)*v0.x + bf_hi(c.x)*v0.y + bf_lo(c.y)*v0.z + bf_hi(c.y)*v0.w
            + bf_lo(c.z)*v1.x + bf_hi(c.z)*v1.y + bf_lo(c.w)*v1.z + bf_hi(c.w)*v1.w;
      }
      #pragma unroll
      for (int o = 16; o; o >>= 1){
        s0 += __shfl_xor_sync(0xffffffffu, s0, o);
        s1 += __shfl_xor_sync(0xffffffffu, s1, o);
      }
      if (lane == 0){
        s0 = fmaxf(s0, 1e-35f); s1 = fmaxf(s1, 1e-35f);
        vout[row0]     = CLOGN - EPSV * __logf(s0);
        vout[row0 + 1] = CLOGN - EPSV * __logf(s1);
        wout[row0]     = 8192.f / s0;     // = exp(vout/eps) exactly
        wout[row0 + 1] = 8192.f / s1;
      }
    }
  } else {
    // ------------- symmetric chains: packed lower-triangle tiles -------------
    int sb  = b - 256;
    int mat = (sb >= NPAIRS) ? 1 : 0;
    int p   = mat ? sb - NPAIRS : sb;
    int A, B; decode_pair(p, A, B);
    bool diag = (A == B);

    const __nv_bfloat16* Ktile = (mat ? g_Kyy : g_Kxx) + (size_t)p * TILE_ELEMS;
    int in = ((t & 1) ^ 1);
    const float* win = mat ? g_why[in] : g_whx[in];
    float* P = mat ? &g_P[1][0][0] : &g_P[0][0][0];

    float* wcol = sbuf;            // 512
    float* wrow = sbuf + TS;       // 512
    float* cs   = sbuf + 2 * TS;   // 8 * 512 staging

    for (int i = tid; i < TS; i += 256){
      wcol[i] = win[B * TS + i];
      wrow[i] = win[A * TS + i];
    }
    __syncthreads();

    float4 acc[4];
    #pragma unroll
    for (int i = 0; i < 4; i++) acc[i] = make_float4(0.f, 0.f, 0.f, 0.f);

    for (int r = wid; r < TS; r += 8){
      const uint4* Kr = reinterpret_cast<const uint4*>(Ktile + ((size_t)r << 9));
      float wr = wrow[r];
      float rd = 0.f;
      #pragma unroll
      for (int i = 0; i < 2; i++){
        uint4 kk = Kr[(i << 5) + lane];
        const float4* wp = reinterpret_cast<const float4*>(wcol + (i << 8) + (lane << 3));
        float4 w0 = wp[0], w1 = wp[1];
        float k0 = bf_lo(kk.x), k1 = bf_hi(kk.x), k2 = bf_lo(kk.y), k3 = bf_hi(kk.y);
        float k4 = bf_lo(kk.z), k5 = bf_hi(kk.z), k6 = bf_lo(kk.w), k7 = bf_hi(kk.w);
        rd += k0*w0.x + k1*w0.y + k2*w0.z + k3*w0.w
            + k4*w1.x + k5*w1.y + k6*w1.z + k7*w1.w;
        if (!diag){
          acc[2*i].x   += k0 * wr;  acc[2*i].y   += k1 * wr;
          acc[2*i].z   += k2 * wr;  acc[2*i].w   += k3 * wr;
          acc[2*i+1].x += k4 * wr;  acc[2*i+1].y += k5 * wr;
          acc[2*i+1].z += k6 * wr;  acc[2*i+1].w += k7 * wr;
        }
      }
      #pragma unroll
      for (int o = 16; o; o >>= 1) rd += __shfl_xor_sync(0xffffffffu, rd, o);
      if (lane == 0)
        P[(((size_t)(A * TS + r)) << 4) + B] = rd;
    }

    if (!diag){
      #pragma unroll
      for (int i = 0; i < 2; i++){
        *reinterpret_cast<float4*>(cs + wid * TS + (i << 8) + (lane << 3))     = acc[2*i];
        *reinterpret_cast<float4*>(cs + wid * TS + (i << 8) + (lane << 3) + 4) = acc[2*i+1];
      }
      __syncthreads();
      for (int c = tid; c < TS; c += 256){
        float s = 0.f;
        #pragma unroll
        for (int w = 0; w < 8; w++) s += cs[w * TS + c];
        P[(((size_t)(B * TS + c)) << 4) + A] = s;
      }
    }
  }
}

// Reduce the 16 partials per row for both symmetric chains; apply transform.
__global__ void __launch_bounds__(256) finish_kernel(int t){
  int idx = blockIdx.x * 256 + threadIdx.x;   // 0..16383
  int mat = idx >> 13;
  int r   = idx & (NPTS - 1);
  const float4* Pp = reinterpret_cast<const float4*>(&g_P[mat][r][0]);
  float4 p0 = Pp[0], p1 = Pp[1], p2 = Pp[2], p3 = Pp[3];
  float s = (p0.x + p0.y + p0.z + p0.w) + (p1.x + p1.y + p1.z + p1.w)
          + (p2.x + p2.y + p2.z + p2.w) + (p3.x + p3.y + p3.z + p3.w);
  s = fmaxf(s, 1e-35f);
  float val = CLOGN - EPSV * __logf(s);
  int out = t & 1;
  if (mat == 0){ g_hx[out][r] = val; g_whx[out][r] = 8192.f / s; }
  else         { g_hy[out][r] = val; g_why[out][r] = 8192.f / s; }
}

__global__ void final_kernel(float* out){
  __shared__ float sred[8];
  int tid = threadIdx.x, lane = tid & 31, wid = tid >> 5;
  const float* arrs[7] = { g_f, g_g, g_hx[0], g_hx[1], g_hy[0], g_hy[1], g_cham };
  float totals[7];
  for (int a = 0; a < 7; a++){
    float s = 0.f;
    for (int i = tid; i < NPTS; i += 256) s += arrs[a][i];
    #pragma unroll
    for (int o = 16; o; o >>= 1) s += __shfl_xor_sync(0xffffffffu, s, o);
    __syncthreads();
    if (lane == 0) sred[wid] = s;
    __syncthreads();
    if (tid == 0){
      float tt = 0.f;
      #pragma unroll
      for (int w = 0; w < 8; w++) tt += sred[w];
      totals[a] = tt;
    }
  }
  if (tid == 0){
    const float invN = 1.f / (float)NPTS;
    float ot_xy = (totals[0] + totals[1]) * invN;
    float ot_xx = (totals[2] + totals[3]) * invN;
    float ot_yy = (totals[4] + totals[5]) * invN;
    float cham  = totals[6] * invN;
    float emd = ot_xy - 0.5f * ot_xx - 0.5f * ot_yy;
    out[0] = 0.2f * cham + 0.8f * emd;
  }
}

extern "C" void kernel_launch(void* const* d_in, const int* in_sizes, int n_in,
                              void* d_out, int out_size){
  const float* pred = (const float*)d_in[0];
  const float* gt   = (const float*)d_in[1];
  float* out = (float*)d_out;

  init_kernel<<<32, 256>>>();
  fill_kernel<<<NPTS, 256>>>(pred, gt,   0);       // Kxy
  fill_kernel<<<NPTS, 256>>>(gt,   pred, 1);       // Kyx + chamfer row mins
  fill_sym_kernel<<<2 * NPAIRS * 64, 256>>>(pred, gt);  // packed Kxx + Kyy

  for (int t = 0; t < 100; t++){
    step_kernel<<<256 + 2 * NPAIRS, 256>>>(t);
    finish_kernel<<<64, 256>>>(t);
  }

  final_kernel<<<1, 256>>>(out);
}